// round 16
// baseline (speedup 1.0000x reference)
#include <cuda_runtime.h>
#include <math.h>

#define NBLK 384
#define BT_LL  32768LL          // B*T
#define BTV_LL 16777216LL       // B*T*V

// ---------------- scratch (static device globals; no allocation) -------------
__device__ float g_xd[16777216];     // pre-gathered emb[tokens]: [128][256][512]
__device__ float g_h_enc[786432];    // 3 layers x 2 parity x [128,1024]
__device__ float g_c_enc[393216];
__device__ float g_h_dec[786432];
__device__ float g_c_dec[393216];
__device__ float g_z[9437184];       // 3 layer slabs x 6 K-partials x [128,4096]
__device__ float g_lat[32768];       // [128,256]
__device__ float g_y[33554432];      // [128,256,1024]
__device__ float g_logits[16777216]; // [128,256,512]
__device__ unsigned g_bar_count, g_bar_phase;

// split-K x6 boundaries (all deltas /32): kind 0->KT1536, 1->KT2048, 2->KT1792
__constant__ int c_off[3][7] = {
    {0, 256, 512, 768, 1024, 1280, 1536},
    {0, 352, 704, 1056, 1408, 1728, 2048},
    {0, 320, 640, 928, 1216, 1504, 1792}};

struct Params {
    const float* Wx[6]; const float* Wh[6]; const float* b[6];
    const float* w_mean; const float* b_mean;
    const float* w_sigma; const float* b_sigma;
    const float* eps;
};

__device__ __forceinline__ float4 ldf4(const float* p) {
    return *reinterpret_cast<const float4*>(p);
}
__device__ __forceinline__ float4 ldcg4(const float* p) {
    float4 v;
    asm volatile("ld.global.cg.v4.f32 {%0,%1,%2,%3},[%4];"
                 : "=f"(v.x), "=f"(v.y), "=f"(v.z), "=f"(v.w) : "l"(p) : "memory");
    return v;
}
__device__ __forceinline__ float ldcg1(const float* p) {
    float v; asm volatile("ld.global.cg.f32 %0,[%1];" : "=f"(v) : "l"(p) : "memory");
    return v;
}
__device__ __forceinline__ unsigned atom_add_acqrel(unsigned* p, unsigned v) {
    unsigned o; asm volatile("atom.add.acq_rel.gpu.global.u32 %0,[%1],%2;"
                             : "=r"(o) : "l"(p), "r"(v) : "memory"); return o;
}
__device__ __forceinline__ void atom_add_release(unsigned* p, unsigned v) {
    unsigned o; asm volatile("atom.add.release.gpu.global.u32 %0,[%1],%2;"
                             : "=r"(o) : "l"(p), "r"(v) : "memory");
}
__device__ __forceinline__ unsigned ld_acquire(const unsigned* p) {
    unsigned v; asm volatile("ld.acquire.gpu.global.u32 %0,[%1];"
                             : "=r"(v) : "l"(p) : "memory"); return v;
}
__device__ __forceinline__ void st_relaxed(unsigned* p, unsigned v) {
    asm volatile("st.relaxed.gpu.global.u32 [%0],%1;" :: "l"(p), "r"(v) : "memory");
}

// Grid barrier (validated R4-R15). 384 blocks co-resident by construction:
// launch_bounds(256,3) caps regs at 85; smem 50KB x3 = 150KB <= 228KB.
__device__ __forceinline__ void grid_barrier() {
    __syncthreads();
    if (threadIdx.x == 0) {
        unsigned gen = ld_acquire(&g_bar_phase);
        if (atom_add_acqrel(&g_bar_count, 1u) == NBLK - 1u) {
            st_relaxed(&g_bar_count, 0u);
            atom_add_release(&g_bar_phase, 1u);
        } else {
            while (ld_acquire(&g_bar_phase) == gen) {}
        }
    }
    __syncthreads();
}

// A-operand fetch (R14-validated): mode 0: A1 dense h; mode 1: A1 = xd (K1=512);
// mode 2: A1 = [lat(256)|xd(512)] (K1=768). A2 = this layer's prev-parity h.
__device__ __forceinline__ float4 fetchA(
    int mode, int K1, const float* A1, const float* A2,
    const float* __restrict__ xd, int t, int gm, int gk)
{
    if (gk >= K1) return ldcg4(A2 + gm * 1024 + (gk - K1));
    if (mode == 0) return ldcg4(A1 + gm * 1024 + gk);
    if (mode == 1) return ldf4(xd + ((size_t)gm * 256 + t) * 512 + gk);
    if (gk < 256) return ldcg4(g_lat + gm * 256 + gk);
    return ldf4(xd + ((size_t)gm * 256 + t) * 512 + (gk - 256));
}

// Split-K x6 GEMM: R14-validated BM128 x BN64 / 8x4-per-thread core with
// BK=32 DOUBLE-BUFFERED smem (1 sync per 32-k) -- only the K partition and
// occupancy changed vs R14.
__device__ void gemm_step(
    float* sA, float* sB, int bid, int mode, int K1, int kind,
    const float* __restrict__ Wx, const float* __restrict__ Wh,
    const float* A1, const float* A2, float* __restrict__ Z,
    int t, const float* __restrict__ xd)
{
    const int tid = threadIdx.x;
    const int part = bid >> 6;                  // 0..5
    const int col0 = (bid & 63) * 64;
    const int kbase = c_off[kind][part];
    const int nk = c_off[kind][part + 1] - kbase;
    Z += part * 524288;

    const int tx = tid & 15, ty = tid >> 4;
    const int mA0 = tid >> 2;                   // 0..63 (other half +64)
    const int kqA = (tid & 3) * 4;              // 0,4,8,12 (other half +16)
    const int kkB = tid >> 4, nqB = tid & 15;   // B rows kkB, kkB+16

    float4 a00, a01, a10, a11, b0, b1;

    // ---- prefetch + store k-tile 0 (k 0..31) into buffer 0 ----
    a00 = fetchA(mode, K1, A1, A2, xd, t, mA0,      kbase + kqA);
    a01 = fetchA(mode, K1, A1, A2, xd, t, mA0 + 64, kbase + kqA);
    a10 = fetchA(mode, K1, A1, A2, xd, t, mA0,      kbase + 16 + kqA);
    a11 = fetchA(mode, K1, A1, A2, xd, t, mA0 + 64, kbase + 16 + kqA);
    {
        int gk = kbase + kkB;
        b0 = ldf4(((gk < K1) ? Wx + (size_t)gk * 4096
                             : Wh + (size_t)(gk - K1) * 4096) + col0 + nqB * 4);
        int gk2 = gk + 16;
        b1 = ldf4(((gk2 < K1) ? Wx + (size_t)gk2 * 4096
                              : Wh + (size_t)(gk2 - K1) * 4096) + col0 + nqB * 4);
    }
    {
        float* pa = sA;
        pa[(kqA + 0) * 132 + mA0] = a00.x; pa[(kqA + 1) * 132 + mA0] = a00.y;
        pa[(kqA + 2) * 132 + mA0] = a00.z; pa[(kqA + 3) * 132 + mA0] = a00.w;
        pa[(kqA + 0) * 132 + mA0 + 64] = a01.x; pa[(kqA + 1) * 132 + mA0 + 64] = a01.y;
        pa[(kqA + 2) * 132 + mA0 + 64] = a01.z; pa[(kqA + 3) * 132 + mA0 + 64] = a01.w;
        pa[(16 + kqA + 0) * 132 + mA0] = a10.x; pa[(16 + kqA + 1) * 132 + mA0] = a10.y;
        pa[(16 + kqA + 2) * 132 + mA0] = a10.z; pa[(16 + kqA + 3) * 132 + mA0] = a10.w;
        pa[(16 + kqA + 0) * 132 + mA0 + 64] = a11.x; pa[(16 + kqA + 1) * 132 + mA0 + 64] = a11.y;
        pa[(16 + kqA + 2) * 132 + mA0 + 64] = a11.z; pa[(16 + kqA + 3) * 132 + mA0 + 64] = a11.w;
        *reinterpret_cast<float4*>(sB + kkB * 64 + nqB * 4) = b0;
        *reinterpret_cast<float4*>(sB + (kkB + 16) * 64 + nqB * 4) = b1;
    }
    __syncthreads();

    float acc[8][4];
#pragma unroll
    for (int r = 0; r < 8; r++)
#pragma unroll
        for (int c2 = 0; c2 < 4; c2++) acc[r][c2] = 0.0f;

    const int nt = nk >> 5;
    for (int it = 0; it < nt; it++) {
        const int cur = it & 1;
        const bool more = (it + 1 < nt);
        if (more) {
            const int k0 = kbase + (it + 1) * 32;
            a00 = fetchA(mode, K1, A1, A2, xd, t, mA0,      k0 + kqA);
            a01 = fetchA(mode, K1, A1, A2, xd, t, mA0 + 64, k0 + kqA);
            a10 = fetchA(mode, K1, A1, A2, xd, t, mA0,      k0 + 16 + kqA);
            a11 = fetchA(mode, K1, A1, A2, xd, t, mA0 + 64, k0 + 16 + kqA);
            int gk = k0 + kkB;
            b0 = ldf4(((gk < K1) ? Wx + (size_t)gk * 4096
                                 : Wh + (size_t)(gk - K1) * 4096) + col0 + nqB * 4);
            int gk2 = gk + 16;
            b1 = ldf4(((gk2 < K1) ? Wx + (size_t)gk2 * 4096
                                  : Wh + (size_t)(gk2 - K1) * 4096) + col0 + nqB * 4);
        }
        const float* pa = sA + cur * 4224;
        const float* pb = sB + cur * 2048;
#pragma unroll
        for (int kk = 0; kk < 32; kk++) {
            float4 av0 = ldf4(pa + kk * 132 + ty * 8);
            float4 av1 = ldf4(pa + kk * 132 + ty * 8 + 4);
            float4 bv4 = ldf4(pb + kk * 64 + tx * 4);
            float av[8] = {av0.x, av0.y, av0.z, av0.w, av1.x, av1.y, av1.z, av1.w};
            float bv[4] = {bv4.x, bv4.y, bv4.z, bv4.w};
#pragma unroll
            for (int r = 0; r < 8; r++)
#pragma unroll
                for (int c2 = 0; c2 < 4; c2++)
                    acc[r][c2] = fmaf(av[r], bv[c2], acc[r][c2]);
        }
        if (more) {
            float* pa2 = sA + (cur ^ 1) * 4224;
            pa2[(kqA + 0) * 132 + mA0] = a00.x; pa2[(kqA + 1) * 132 + mA0] = a00.y;
            pa2[(kqA + 2) * 132 + mA0] = a00.z; pa2[(kqA + 3) * 132 + mA0] = a00.w;
            pa2[(kqA + 0) * 132 + mA0 + 64] = a01.x; pa2[(kqA + 1) * 132 + mA0 + 64] = a01.y;
            pa2[(kqA + 2) * 132 + mA0 + 64] = a01.z; pa2[(kqA + 3) * 132 + mA0 + 64] = a01.w;
            pa2[(16 + kqA + 0) * 132 + mA0] = a10.x; pa2[(16 + kqA + 1) * 132 + mA0] = a10.y;
            pa2[(16 + kqA + 2) * 132 + mA0] = a10.z; pa2[(16 + kqA + 3) * 132 + mA0] = a10.w;
            pa2[(16 + kqA + 0) * 132 + mA0 + 64] = a11.x; pa2[(16 + kqA + 1) * 132 + mA0 + 64] = a11.y;
            pa2[(16 + kqA + 2) * 132 + mA0 + 64] = a11.z; pa2[(16 + kqA + 3) * 132 + mA0 + 64] = a11.w;
            float* pb2 = sB + (cur ^ 1) * 2048;
            *reinterpret_cast<float4*>(pb2 + kkB * 64 + nqB * 4) = b0;
            *reinterpret_cast<float4*>(pb2 + (kkB + 16) * 64 + nqB * 4) = b1;
        }
        __syncthreads();
    }

#pragma unroll
    for (int r = 0; r < 8; r++) {
        float4 v = make_float4(acc[r][0], acc[r][1], acc[r][2], acc[r][3]);
        *reinterpret_cast<float4*>(
            Z + (size_t)(ty * 8 + r) * 4096 + col0 + tx * 4) = v;
    }
    __syncthreads();
}

// Cell phase (R14-validated float4 math; now 6 K-partials).
__device__ __forceinline__ void cell_step(
    int gid0, const float* __restrict__ zbase,
    float* __restrict__ h, float* __restrict__ c,
    const float* __restrict__ bias, float* __restrict__ y, int t)
{
    if (gid0 >= 32768) return;
    const int b = gid0 >> 8;
    const int u = (gid0 & 255) * 4;
    const size_t zo = (size_t)b * 4096;
    float4 zi = ldf4(bias + u);
    float4 zf = ldf4(bias + 1024 + u);
    float4 zg = ldf4(bias + 2048 + u);
    float4 zn = ldf4(bias + 3072 + u);
#pragma unroll
    for (int pp = 0; pp < 6; pp++) {
        const float* Zp = zbase + pp * 524288 + zo;
        float4 v;
        v = ldcg4(Zp + u);        zi.x += v.x; zi.y += v.y; zi.z += v.z; zi.w += v.w;
        v = ldcg4(Zp + 1024 + u); zf.x += v.x; zf.y += v.y; zf.z += v.z; zf.w += v.w;
        v = ldcg4(Zp + 2048 + u); zg.x += v.x; zg.y += v.y; zg.z += v.z; zg.w += v.w;
        v = ldcg4(Zp + 3072 + u); zn.x += v.x; zn.y += v.y; zn.z += v.z; zn.w += v.w;
    }
    const int ihc = b * 1024 + u;
    float4 cv = ldf4(c + ihc);
    float4 hv;
    {
        float* zip = &zi.x; float* zfp = &zf.x; float* zgp = &zg.x; float* znp = &zn.x;
        float* cp = &cv.x; float* hp = &hv.x;
#pragma unroll
        for (int e = 0; e < 4; e++) {
            float si = 1.0f / (1.0f + expf(-zip[e]));
            float sf = 1.0f / (1.0f + expf(-zfp[e]));
            float so = 1.0f / (1.0f + expf(-znp[e]));
            float cc = sf * cp[e] + si * tanhf(zgp[e]);
            cp[e] = cc;
            hp[e] = so * tanhf(cc);
        }
    }
    *reinterpret_cast<float4*>(c + ihc) = cv;
    *reinterpret_cast<float4*>(h + ihc) = hv;
    if (y) *reinterpret_cast<float4*>(y + ((size_t)b * 256 + t) * 1024 + u) = hv;
}

// Persistent kernel: wavefront-pipelined (R7/R14-validated scheduler).
__global__ void __launch_bounds__(256, 3) vae_persistent(Params p)
{
    __shared__ __align__(16) float sA[8448];  // 2 x 32 x 132
    __shared__ __align__(16) float sB[4096];  // 2 x 32 x 64

    const int bid = blockIdx.x;
    const int tid = threadIdx.x;
    const int gid0 = bid * 256 + tid;

    for (int i = gid0; i < 786432; i += NBLK * 256) {
        g_h_enc[i] = 0.0f; g_h_dec[i] = 0.0f;
    }
    for (int i = gid0; i < 393216; i += NBLK * 256) {
        g_c_enc[i] = 0.0f; g_c_dec[i] = 0.0f;
    }
    grid_barrier();

    float* const z0 = g_z;
    float* const z1 = g_z + 3145728;
    float* const z2 = g_z + 6291456;

    for (int s = 0; s < 258; s++) {                // encoder wavefronts
        const int pw = s & 1, pr = pw ^ 1;
        if (s < 256)
            gemm_step(sA, sB, bid, 1, 512, 0, p.Wx[0], p.Wh[0],
                      nullptr, g_h_enc + pr * 131072, z0, s, g_xd);
        if (s >= 1 && s <= 256)
            gemm_step(sA, sB, bid, 0, 1024, 1, p.Wx[1], p.Wh[1],
                      g_h_enc + pr * 131072, g_h_enc + (2 + pr) * 131072,
                      z1, s - 1, g_xd);
        if (s >= 2)
            gemm_step(sA, sB, bid, 0, 1024, 1, p.Wx[2], p.Wh[2],
                      g_h_enc + (2 + pr) * 131072, g_h_enc + (4 + pr) * 131072,
                      z2, s - 2, g_xd);
        grid_barrier();
        if (s < 256)
            cell_step(gid0, z0, g_h_enc + pw * 131072, g_c_enc, p.b[0], nullptr, s);
        if (s >= 1 && s <= 256)
            cell_step(gid0, z1, g_h_enc + (2 + pw) * 131072, g_c_enc + 131072,
                      p.b[1], nullptr, s - 1);
        if (s >= 2)
            cell_step(gid0, z2, g_h_enc + (4 + pw) * 131072, g_c_enc + 262144,
                      p.b[2], nullptr, s - 2);
        grid_barrier();
    }

    if (bid < 128) {   // latent: projects CELL state c3; eps ADDED (faithful)
        const float* c3 = g_c_enc + 262144 + bid * 1024;
        for (int i = tid; i < 1024; i += 256) sA[i] = ldcg1(c3 + i);
        __syncthreads();
        float am = 0.f, as = 0.f;
        for (int k = 0; k < 1024; k++) {
            float a = sA[k];
            am = fmaf(a, __ldg(&p.w_mean[k * 256 + tid]), am);
            as = fmaf(a, __ldg(&p.w_sigma[k * 256 + tid]), as);
        }
        float mean = am + __ldg(&p.b_mean[tid]);
        float sg   = as + __ldg(&p.b_sigma[tid]);
        g_lat[bid * 256 + tid] = mean + expf(0.5f * sg)
                               + __ldg(&p.eps[bid * 256 + tid]);
        __syncthreads();
    }
    grid_barrier();

    for (int s = 0; s < 258; s++) {                // decoder wavefronts
        const int pw = s & 1, pr = pw ^ 1;
        if (s < 256)
            gemm_step(sA, sB, bid, 2, 768, 2, p.Wx[3], p.Wh[3],
                      nullptr, g_h_dec + pr * 131072, z0, s, g_xd);
        if (s >= 1 && s <= 256)
            gemm_step(sA, sB, bid, 0, 1024, 1, p.Wx[4], p.Wh[4],
                      g_h_dec + pr * 131072, g_h_dec + (2 + pr) * 131072,
                      z1, s - 1, g_xd);
        if (s >= 2)
            gemm_step(sA, sB, bid, 0, 1024, 1, p.Wx[5], p.Wh[5],
                      g_h_dec + (2 + pr) * 131072, g_h_dec + (4 + pr) * 131072,
                      z2, s - 2, g_xd);
        grid_barrier();
        if (s < 256)
            cell_step(gid0, z0, g_h_dec + pw * 131072, g_c_dec, p.b[3], nullptr, s);
        if (s >= 1 && s <= 256)
            cell_step(gid0, z1, g_h_dec + (2 + pw) * 131072, g_c_dec + 131072,
                      p.b[4], nullptr, s - 1);
        if (s >= 2)
            cell_step(gid0, z2, g_h_dec + (4 + pw) * 131072, g_c_dec + 262144,
                      p.b[5], g_y, s - 2);
        grid_barrier();
    }
}

// pre-gather embeddings: g_xd[b][t][v] = emb[tokens[b][t]][v]
__global__ void prep_x(const int* __restrict__ tokens, const float* __restrict__ emb)
{
    int idx = blockIdx.x * 256 + threadIdx.x;
    int b = idx >> 15, t = (idx >> 7) & 255, v4 = idx & 127;
    int tok = __ldg(&tokens[b * 256 + t]);
    *reinterpret_cast<float4*>(g_xd + (size_t)idx * 4) =
        ldf4(emb + (size_t)tok * 512 + v4 * 4);
}

// Dense logits GEMM (validated R4-R15): Z[32768,512] = Y @ W[1024,512] + b.
__global__ void __launch_bounds__(128) logits_gemm(
    const float* __restrict__ A, const float* __restrict__ W,
    const float* __restrict__ bias, float* __restrict__ Z)
{
    __shared__ __align__(16) float As[16][68];
    __shared__ __align__(16) float Bs[16][64];
    const int tid = threadIdx.x;
    const int tx = tid & 15, ty = tid >> 4;
    const int row0 = blockIdx.y * 64, col0 = blockIdx.x * 64;
    float4 pa[2], pb[2];
#pragma unroll
    for (int j = 0; j < 2; j++) {
        int c = tid + j * 128;
        pa[j] = ldf4(A + (size_t)(row0 + (c >> 2)) * 1024 + (c & 3) * 4);
        pb[j] = ldf4(W + (size_t)(c >> 4) * 512 + col0 + (c & 15) * 4);
    }
#pragma unroll
    for (int j = 0; j < 2; j++) {
        int c = tid + j * 128;
        int m = c >> 2, kb = (c & 3) * 4;
        As[kb + 0][m] = pa[j].x; As[kb + 1][m] = pa[j].y;
        As[kb + 2][m] = pa[j].z; As[kb + 3][m] = pa[j].w;
        *reinterpret_cast<float4*>(&Bs[c >> 4][(c & 15) * 4]) = pb[j];
    }
    __syncthreads();
    float acc[8][4];
#pragma unroll
    for (int r = 0; r < 8; r++)
#pragma unroll
        for (int c2 = 0; c2 < 4; c2++) acc[r][c2] = 0.0f;
    for (int k0 = 16;; k0 += 16) {
        const bool more = (k0 < 1024);
        if (more) {
#pragma unroll
            for (int j = 0; j < 2; j++) {
                int c = tid + j * 128;
                pa[j] = ldf4(A + (size_t)(row0 + (c >> 2)) * 1024 + k0 + (c & 3) * 4);
                pb[j] = ldf4(W + (size_t)(k0 + (c >> 4)) * 512 + col0 + (c & 15) * 4);
            }
        }
#pragma unroll
        for (int kk = 0; kk < 16; kk++) {
            float4 a0 = ldf4(&As[kk][ty * 8]);
            float4 a1 = ldf4(&As[kk][ty * 8 + 4]);
            float4 b  = ldf4(&Bs[kk][tx * 4]);
            float av[8] = {a0.x, a0.y, a0.z, a0.w, a1.x, a1.y, a1.z, a1.w};
            float bv[4] = {b.x, b.y, b.z, b.w};
#pragma unroll
            for (int r = 0; r < 8; r++)
#pragma unroll
                for (int c2 = 0; c2 < 4; c2++)
                    acc[r][c2] = fmaf(av[r], bv[c2], acc[r][c2]);
        }
        if (!more) break;
        __syncthreads();
#pragma unroll
        for (int j = 0; j < 2; j++) {
            int c = tid + j * 128;
            int m = c >> 2, kb = (c & 3) * 4;
            As[kb + 0][m] = pa[j].x; As[kb + 1][m] = pa[j].y;
            As[kb + 2][m] = pa[j].z; As[kb + 3][m] = pa[j].w;
            *reinterpret_cast<float4*>(&Bs[c >> 4][(c & 15) * 4]) = pb[j];
        }
        __syncthreads();
    }
    float4 bv4 = ldf4(bias + col0 + tx * 4);
#pragma unroll
    for (int r = 0; r < 8; r++) {
        float4 v = make_float4(acc[r][0] + bv4.x, acc[r][1] + bv4.y,
                               acc[r][2] + bv4.z, acc[r][3] + bv4.w);
        *reinterpret_cast<float4*>(Z + (size_t)(row0 + ty * 8 + r) * 512 + col0 + tx * 4) = v;
    }
}

// argmax (first-occurrence) + logits emission (validated R4-R15).
__global__ void emit_kernel(const float* __restrict__ logits,
                            float* __restrict__ out, long long out_size)
{
    int row = blockIdx.x, tid = threadIdx.x;
    const float* lr = logits + (size_t)row * 512;
    float best = -3.402823466e38f; int bi = 0;
#pragma unroll
    for (int j = 0; j < 4; j++) {
        int vi = tid + j * 128; float v = lr[vi];
        if (v > best) { best = v; bi = vi; }
    }
    __shared__ float sv[128]; __shared__ int si[128];
    sv[tid] = best; si[tid] = bi;
    __syncthreads();
    for (int s = 64; s > 0; s >>= 1) {
        if (tid < s) {
            float v2 = sv[tid + s]; int i2 = si[tid + s];
            if (v2 > sv[tid] || (v2 == sv[tid] && i2 < si[tid])) { sv[tid] = v2; si[tid] = i2; }
        }
        __syncthreads();
    }
    int amax = si[0];
    if (out_size == BT_LL + BTV_LL) {
        if (tid == 0) out[row] = (float)amax;
        float* lo = out + BT_LL + (size_t)row * 512;
#pragma unroll
        for (int j = 0; j < 4; j++) lo[tid + j * 128] = lr[tid + j * 128];
    } else if (out_size == BTV_LL) {
        float* lo = out + (size_t)row * 512;
#pragma unroll
        for (int j = 0; j < 4; j++) lo[tid + j * 128] = lr[tid + j * 128];
    } else if (out_size == BT_LL) {
        if (tid == 0) reinterpret_cast<int*>(out)[row] = amax;
    } else {
        if (tid == 0 && (long long)row < out_size) out[row] = (float)amax;
#pragma unroll
        for (int j = 0; j < 4; j++) {
            long long o = BT_LL + (long long)row * 512 + tid + j * 128;
            if (o < out_size) out[o] = lr[tid + j * 128];
        }
    }
}

extern "C" void kernel_launch(void* const* d_in, const int* in_sizes, int n_in,
                              void* d_out, int out_size)
{
    Params p;
    const int* tokens = (const int*)d_in[0];
    const float* emb  = (const float*)d_in[1];
    for (int l = 0; l < 6; l++) {
        p.Wx[l] = (const float*)d_in[2 + l * 3];
        p.Wh[l] = (const float*)d_in[3 + l * 3];
        p.b[l]  = (const float*)d_in[4 + l * 3];
    }
    p.w_mean  = (const float*)d_in[20];
    p.b_mean  = (const float*)d_in[21];
    p.w_sigma = (const float*)d_in[22];
    p.b_sigma = (const float*)d_in[23];
    const float* dec_w = (const float*)d_in[24];
    const float* dec_b = (const float*)d_in[25];
    p.eps = (const float*)d_in[26];

    float *y, *lg;
    cudaGetSymbolAddress((void**)&y,  g_y);
    cudaGetSymbolAddress((void**)&lg, g_logits);

    prep_x<<<16384, 256>>>(tokens, emb);
    vae_persistent<<<NBLK, 256>>>(p);
    logits_gemm<<<dim3(8, 512), 128>>>(y, dec_w, dec_b, lg);
    emit_kernel<<<32768, 128>>>(lg, (float*)d_out, (long long)out_size);
}

// round 17
// speedup vs baseline: 1.1316x; 1.1316x over previous
#include <cuda_runtime.h>
#include <math.h>

#define NBLK 256
#define BT_LL  32768LL          // B*T
#define BTV_LL 16777216LL       // B*T*V

// ---------------- scratch (static device globals; no allocation) -------------
__device__ float g_xd[16777216];     // pre-gathered emb[tokens]: [128][256][512]
__device__ float g_h_enc[786432];    // 3 layers x 2 parity x [128,1024]
__device__ float g_c_enc[393216];
__device__ float g_h_dec[786432];
__device__ float g_c_dec[393216];
__device__ float g_z[12582912];      // 3 layer slabs x 8 K-partials x [128,4096]
__device__ float g_lat[32768];       // [128,256]
__device__ float g_y[33554432];      // [128,256,1024]
__device__ float g_logits[16777216]; // [128,256,512]
__device__ unsigned g_bar_count, g_bar_phase;

struct Params {
    const float* Wx[6]; const float* Wh[6]; const float* b[6];
    const float* w_mean; const float* b_mean;
    const float* w_sigma; const float* b_sigma;
    const float* eps;
};

__device__ __forceinline__ float4 ldf4(const float* p) {
    return *reinterpret_cast<const float4*>(p);
}
__device__ __forceinline__ float4 ldcg4(const float* p) {
    float4 v;
    asm volatile("ld.global.cg.v4.f32 {%0,%1,%2,%3},[%4];"
                 : "=f"(v.x), "=f"(v.y), "=f"(v.z), "=f"(v.w) : "l"(p) : "memory");
    return v;
}
__device__ __forceinline__ float ldcg1(const float* p) {
    float v; asm volatile("ld.global.cg.f32 %0,[%1];" : "=f"(v) : "l"(p) : "memory");
    return v;
}
__device__ __forceinline__ unsigned atom_add_acqrel(unsigned* p, unsigned v) {
    unsigned o; asm volatile("atom.add.acq_rel.gpu.global.u32 %0,[%1],%2;"
                             : "=r"(o) : "l"(p), "r"(v) : "memory"); return o;
}
__device__ __forceinline__ void atom_add_release(unsigned* p, unsigned v) {
    unsigned o; asm volatile("atom.add.release.gpu.global.u32 %0,[%1],%2;"
                             : "=r"(o) : "l"(p), "r"(v) : "memory");
}
__device__ __forceinline__ unsigned ld_acquire(const unsigned* p) {
    unsigned v; asm volatile("ld.acquire.gpu.global.u32 %0,[%1];"
                             : "=r"(v) : "l"(p) : "memory"); return v;
}
__device__ __forceinline__ void st_relaxed(unsigned* p, unsigned v) {
    asm volatile("st.relaxed.gpu.global.u32 [%0],%1;" :: "l"(p), "r"(v) : "memory");
}

// Grid barrier (validated R4-R16). 256 blocks co-resident: launch_bounds(256,2)
// caps regs at 128; static smem 33KB x2 = 66KB <= 228KB -> 2 blocks/SM.
__device__ __forceinline__ void grid_barrier() {
    __syncthreads();
    if (threadIdx.x == 0) {
        unsigned gen = ld_acquire(&g_bar_phase);
        if (atom_add_acqrel(&g_bar_count, 1u) == NBLK - 1u) {
            st_relaxed(&g_bar_count, 0u);
            atom_add_release(&g_bar_phase, 1u);
        } else {
            while (ld_acquire(&g_bar_phase) == gen) {}
        }
    }
    __syncthreads();
}

// A-operand fetch (R14-validated): mode 0: A1 dense h; mode 1: A1 = xd (K1=512);
// mode 2: A1 = [lat(256)|xd(512)] (K1=768). A2 = this layer's prev-parity h.
__device__ __forceinline__ float4 fetchA(
    int mode, int K1, const float* A1, const float* A2,
    const float* __restrict__ xd, int t, int gm, int gk)
{
    if (gk >= K1) return ldcg4(A2 + gm * 1024 + (gk - K1));
    if (mode == 0) return ldcg4(A1 + gm * 1024 + gk);
    if (mode == 1) return ldf4(xd + ((size_t)gm * 256 + t) * 512 + gk);
    if (gk < 256) return ldcg4(g_lat + gm * 256 + gk);
    return ldf4(xd + ((size_t)gm * 256 + t) * 512 + (gk - 256));
}

// Split-K x8 GEMM: BM128 x BN128, 8x8 per thread (cols split tx*4 / 64+tx*4),
// BK=16 double-buffered smem, one sync per k-tile. 256 blocks = 32 col x 8 K.
__device__ void gemm_step(
    float* sA, float* sB, int bid, int mode, int K1, int KT,
    const float* __restrict__ Wx, const float* __restrict__ Wh,
    const float* A1, const float* A2, float* __restrict__ Z,
    int t, const float* __restrict__ xd)
{
    const int tid = threadIdx.x;
    const int part = bid >> 5;                  // 0..7
    const int col0 = (bid & 31) * 128;
    const int kq8 = KT >> 3;                    // 192 / 256 / 224 (all /16)
    const int kbase = part * kq8;
    Z += part * 524288;

    const int tx = tid & 15, ty = tid >> 4;     // rows ty*8..+8
    const int mA0 = tid >> 2;                   // A chunk row (0..63; +64 for j=1)
    const int kqA = (tid & 3) * 4;              // 0,4,8,12
    const int kkB = tid >> 5, nqB = tid & 31;   // B: rows kkB, kkB+8

    float4 a0c, a1c, b0c, b1c;

    // ---- prefetch + store k-tile 0 into buffer 0 ----
    a0c = fetchA(mode, K1, A1, A2, xd, t, mA0,      kbase + kqA);
    a1c = fetchA(mode, K1, A1, A2, xd, t, mA0 + 64, kbase + kqA);
    {
        int gk = kbase + kkB;
        b0c = ldf4(((gk < K1) ? Wx + (size_t)gk * 4096
                              : Wh + (size_t)(gk - K1) * 4096) + col0 + nqB * 4);
        int gk2 = gk + 8;
        b1c = ldf4(((gk2 < K1) ? Wx + (size_t)gk2 * 4096
                               : Wh + (size_t)(gk2 - K1) * 4096) + col0 + nqB * 4);
    }
    {
        float* pa = sA;
        pa[(kqA + 0) * 132 + mA0] = a0c.x; pa[(kqA + 1) * 132 + mA0] = a0c.y;
        pa[(kqA + 2) * 132 + mA0] = a0c.z; pa[(kqA + 3) * 132 + mA0] = a0c.w;
        pa[(kqA + 0) * 132 + mA0 + 64] = a1c.x; pa[(kqA + 1) * 132 + mA0 + 64] = a1c.y;
        pa[(kqA + 2) * 132 + mA0 + 64] = a1c.z; pa[(kqA + 3) * 132 + mA0 + 64] = a1c.w;
        *reinterpret_cast<float4*>(sB + kkB * 132 + nqB * 4) = b0c;
        *reinterpret_cast<float4*>(sB + (kkB + 8) * 132 + nqB * 4) = b1c;
    }
    __syncthreads();

    float acc[8][8];
#pragma unroll
    for (int r = 0; r < 8; r++)
#pragma unroll
        for (int c2 = 0; c2 < 8; c2++) acc[r][c2] = 0.0f;

    const int nt = kq8 >> 4;
    for (int it = 0; it < nt; it++) {
        const int cur = it & 1;
        const bool more = (it + 1 < nt);
        if (more) {
            const int k0 = kbase + (it + 1) * 16;
            a0c = fetchA(mode, K1, A1, A2, xd, t, mA0,      k0 + kqA);
            a1c = fetchA(mode, K1, A1, A2, xd, t, mA0 + 64, k0 + kqA);
            int gk = k0 + kkB;
            b0c = ldf4(((gk < K1) ? Wx + (size_t)gk * 4096
                                  : Wh + (size_t)(gk - K1) * 4096) + col0 + nqB * 4);
            int gk2 = gk + 8;
            b1c = ldf4(((gk2 < K1) ? Wx + (size_t)gk2 * 4096
                                   : Wh + (size_t)(gk2 - K1) * 4096) + col0 + nqB * 4);
        }
        const float* pa = sA + cur * 2112;
        const float* pb = sB + cur * 2112;
#pragma unroll
        for (int kk = 0; kk < 16; kk++) {
            float4 av0 = ldf4(pa + kk * 132 + ty * 8);
            float4 av1 = ldf4(pa + kk * 132 + ty * 8 + 4);
            float4 bv0 = ldf4(pb + kk * 132 + tx * 4);
            float4 bv1 = ldf4(pb + kk * 132 + 64 + tx * 4);
            float av[8] = {av0.x, av0.y, av0.z, av0.w, av1.x, av1.y, av1.z, av1.w};
            float bv[8] = {bv0.x, bv0.y, bv0.z, bv0.w, bv1.x, bv1.y, bv1.z, bv1.w};
#pragma unroll
            for (int r = 0; r < 8; r++)
#pragma unroll
                for (int c2 = 0; c2 < 8; c2++)
                    acc[r][c2] = fmaf(av[r], bv[c2], acc[r][c2]);
        }
        if (more) {
            float* pa2 = sA + (cur ^ 1) * 2112;
            pa2[(kqA + 0) * 132 + mA0] = a0c.x; pa2[(kqA + 1) * 132 + mA0] = a0c.y;
            pa2[(kqA + 2) * 132 + mA0] = a0c.z; pa2[(kqA + 3) * 132 + mA0] = a0c.w;
            pa2[(kqA + 0) * 132 + mA0 + 64] = a1c.x; pa2[(kqA + 1) * 132 + mA0 + 64] = a1c.y;
            pa2[(kqA + 2) * 132 + mA0 + 64] = a1c.z; pa2[(kqA + 3) * 132 + mA0 + 64] = a1c.w;
            float* pb2 = sB + (cur ^ 1) * 2112;
            *reinterpret_cast<float4*>(pb2 + kkB * 132 + nqB * 4) = b0c;
            *reinterpret_cast<float4*>(pb2 + (kkB + 8) * 132 + nqB * 4) = b1c;
        }
        __syncthreads();
    }

#pragma unroll
    for (int r = 0; r < 8; r++) {
        float* zr = Z + (size_t)(ty * 8 + r) * 4096 + col0;
        *reinterpret_cast<float4*>(zr + tx * 4) =
            make_float4(acc[r][0], acc[r][1], acc[r][2], acc[r][3]);
        *reinterpret_cast<float4*>(zr + 64 + tx * 4) =
            make_float4(acc[r][4], acc[r][5], acc[r][6], acc[r][7]);
    }
    __syncthreads();
}

// Cell phase (R14-validated float4 math; 8 K-partials).
__device__ __forceinline__ void cell_step(
    int gid0, const float* __restrict__ zbase,
    float* __restrict__ h, float* __restrict__ c,
    const float* __restrict__ bias, float* __restrict__ y, int t)
{
    if (gid0 >= 32768) return;
    const int b = gid0 >> 8;
    const int u = (gid0 & 255) * 4;
    const size_t zo = (size_t)b * 4096;
    float4 zi = ldf4(bias + u);
    float4 zf = ldf4(bias + 1024 + u);
    float4 zg = ldf4(bias + 2048 + u);
    float4 zn = ldf4(bias + 3072 + u);
#pragma unroll
    for (int pp = 0; pp < 8; pp++) {
        const float* Zp = zbase + pp * 524288 + zo;
        float4 v;
        v = ldcg4(Zp + u);        zi.x += v.x; zi.y += v.y; zi.z += v.z; zi.w += v.w;
        v = ldcg4(Zp + 1024 + u); zf.x += v.x; zf.y += v.y; zf.z += v.z; zf.w += v.w;
        v = ldcg4(Zp + 2048 + u); zg.x += v.x; zg.y += v.y; zg.z += v.z; zg.w += v.w;
        v = ldcg4(Zp + 3072 + u); zn.x += v.x; zn.y += v.y; zn.z += v.z; zn.w += v.w;
    }
    const int ihc = b * 1024 + u;
    float4 cv = ldf4(c + ihc);
    float4 hv;
    {
        float* zip = &zi.x; float* zfp = &zf.x; float* zgp = &zg.x; float* znp = &zn.x;
        float* cp = &cv.x; float* hp = &hv.x;
#pragma unroll
        for (int e = 0; e < 4; e++) {
            float si = 1.0f / (1.0f + expf(-zip[e]));
            float sf = 1.0f / (1.0f + expf(-zfp[e]));
            float so = 1.0f / (1.0f + expf(-znp[e]));
            float cc = sf * cp[e] + si * tanhf(zgp[e]);
            cp[e] = cc;
            hp[e] = so * tanhf(cc);
        }
    }
    *reinterpret_cast<float4*>(c + ihc) = cv;
    *reinterpret_cast<float4*>(h + ihc) = hv;
    if (y) *reinterpret_cast<float4*>(y + ((size_t)b * 256 + t) * 1024 + u) = hv;
}

// Persistent kernel: wavefront-pipelined (R7/R14-validated scheduler).
__global__ void __launch_bounds__(256, 2) vae_persistent(Params p)
{
    __shared__ __align__(16) float sA[4224];  // 2 x 16 x 132
    __shared__ __align__(16) float sB[4224];  // 2 x 16 x 132 (rows of 128 + pad)

    const int bid = blockIdx.x;
    const int tid = threadIdx.x;
    const int gid0 = bid * 256 + tid;

    for (int i = gid0; i < 786432; i += NBLK * 256) {
        g_h_enc[i] = 0.0f; g_h_dec[i] = 0.0f;
    }
    for (int i = gid0; i < 393216; i += NBLK * 256) {
        g_c_enc[i] = 0.0f; g_c_dec[i] = 0.0f;
    }
    grid_barrier();

    float* const z0 = g_z;
    float* const z1 = g_z + 4194304;
    float* const z2 = g_z + 8388608;

    for (int s = 0; s < 258; s++) {                // encoder wavefronts
        const int pw = s & 1, pr = pw ^ 1;
        if (s < 256)
            gemm_step(sA, sB, bid, 1, 512, 1536, p.Wx[0], p.Wh[0],
                      nullptr, g_h_enc + pr * 131072, z0, s, g_xd);
        if (s >= 1 && s <= 256)
            gemm_step(sA, sB, bid, 0, 1024, 2048, p.Wx[1], p.Wh[1],
                      g_h_enc + pr * 131072, g_h_enc + (2 + pr) * 131072,
                      z1, s - 1, g_xd);
        if (s >= 2)
            gemm_step(sA, sB, bid, 0, 1024, 2048, p.Wx[2], p.Wh[2],
                      g_h_enc + (2 + pr) * 131072, g_h_enc + (4 + pr) * 131072,
                      z2, s - 2, g_xd);
        grid_barrier();
        if (s < 256)
            cell_step(gid0, z0, g_h_enc + pw * 131072, g_c_enc, p.b[0], nullptr, s);
        if (s >= 1 && s <= 256)
            cell_step(gid0, z1, g_h_enc + (2 + pw) * 131072, g_c_enc + 131072,
                      p.b[1], nullptr, s - 1);
        if (s >= 2)
            cell_step(gid0, z2, g_h_enc + (4 + pw) * 131072, g_c_enc + 262144,
                      p.b[2], nullptr, s - 2);
        grid_barrier();
    }

    if (bid < 128) {   // latent: projects CELL state c3; eps ADDED (faithful)
        const float* c3 = g_c_enc + 262144 + bid * 1024;
        for (int i = tid; i < 1024; i += 256) sA[i] = ldcg1(c3 + i);
        __syncthreads();
        float am = 0.f, as = 0.f;
        for (int k = 0; k < 1024; k++) {
            float a = sA[k];
            am = fmaf(a, __ldg(&p.w_mean[k * 256 + tid]), am);
            as = fmaf(a, __ldg(&p.w_sigma[k * 256 + tid]), as);
        }
        float mean = am + __ldg(&p.b_mean[tid]);
        float sg   = as + __ldg(&p.b_sigma[tid]);
        g_lat[bid * 256 + tid] = mean + expf(0.5f * sg)
                               + __ldg(&p.eps[bid * 256 + tid]);
        __syncthreads();
    }
    grid_barrier();

    for (int s = 0; s < 258; s++) {                // decoder wavefronts
        const int pw = s & 1, pr = pw ^ 1;
        if (s < 256)
            gemm_step(sA, sB, bid, 2, 768, 1792, p.Wx[3], p.Wh[3],
                      nullptr, g_h_dec + pr * 131072, z0, s, g_xd);
        if (s >= 1 && s <= 256)
            gemm_step(sA, sB, bid, 0, 1024, 2048, p.Wx[4], p.Wh[4],
                      g_h_dec + pr * 131072, g_h_dec + (2 + pr) * 131072,
                      z1, s - 1, g_xd);
        if (s >= 2)
            gemm_step(sA, sB, bid, 0, 1024, 2048, p.Wx[5], p.Wh[5],
                      g_h_dec + (2 + pr) * 131072, g_h_dec + (4 + pr) * 131072,
                      z2, s - 2, g_xd);
        grid_barrier();
        if (s < 256)
            cell_step(gid0, z0, g_h_dec + pw * 131072, g_c_dec, p.b[3], nullptr, s);
        if (s >= 1 && s <= 256)
            cell_step(gid0, z1, g_h_dec + (2 + pw) * 131072, g_c_dec + 131072,
                      p.b[4], nullptr, s - 1);
        if (s >= 2)
            cell_step(gid0, z2, g_h_dec + (4 + pw) * 131072, g_c_dec + 262144,
                      p.b[5], g_y, s - 2);
        grid_barrier();
    }
}

// pre-gather embeddings: g_xd[b][t][v] = emb[tokens[b][t]][v]
__global__ void prep_x(const int* __restrict__ tokens, const float* __restrict__ emb)
{
    int idx = blockIdx.x * 256 + threadIdx.x;
    int b = idx >> 15, t = (idx >> 7) & 255, v4 = idx & 127;
    int tok = __ldg(&tokens[b * 256 + t]);
    *reinterpret_cast<float4*>(g_xd + (size_t)idx * 4) =
        ldf4(emb + (size_t)tok * 512 + v4 * 4);
}

// Dense logits GEMM (validated R4-R16): Z[32768,512] = Y @ W[1024,512] + b.
__global__ void __launch_bounds__(128) logits_gemm(
    const float* __restrict__ A, const float* __restrict__ W,
    const float* __restrict__ bias, float* __restrict__ Z)
{
    __shared__ __align__(16) float As[16][68];
    __shared__ __align__(16) float Bs[16][64];
    const int tid = threadIdx.x;
    const int tx = tid & 15, ty = tid >> 4;
    const int row0 = blockIdx.y * 64, col0 = blockIdx.x * 64;
    float4 pa[2], pb[2];
#pragma unroll
    for (int j = 0; j < 2; j++) {
        int c = tid + j * 128;
        pa[j] = ldf4(A + (size_t)(row0 + (c >> 2)) * 1024 + (c & 3) * 4);
        pb[j] = ldf4(W + (size_t)(c >> 4) * 512 + col0 + (c & 15) * 4);
    }
#pragma unroll
    for (int j = 0; j < 2; j++) {
        int c = tid + j * 128;
        int m = c >> 2, kb = (c & 3) * 4;
        As[kb + 0][m] = pa[j].x; As[kb + 1][m] = pa[j].y;
        As[kb + 2][m] = pa[j].z; As[kb + 3][m] = pa[j].w;
        *reinterpret_cast<float4*>(&Bs[c >> 4][(c & 15) * 4]) = pb[j];
    }
    __syncthreads();
    float acc[8][4];
#pragma unroll
    for (int r = 0; r < 8; r++)
#pragma unroll
        for (int c2 = 0; c2 < 4; c2++) acc[r][c2] = 0.0f;
    for (int k0 = 16;; k0 += 16) {
        const bool more = (k0 < 1024);
        if (more) {
#pragma unroll
            for (int j = 0; j < 2; j++) {
                int c = tid + j * 128;
                pa[j] = ldf4(A + (size_t)(row0 + (c >> 2)) * 1024 + k0 + (c & 3) * 4);
                pb[j] = ldf4(W + (size_t)(k0 + (c >> 4)) * 512 + col0 + (c & 15) * 4);
            }
        }
#pragma unroll
        for (int kk = 0; kk < 16; kk++) {
            float4 a0 = ldf4(&As[kk][ty * 8]);
            float4 a1 = ldf4(&As[kk][ty * 8 + 4]);
            float4 b  = ldf4(&Bs[kk][tx * 4]);
            float av[8] = {a0.x, a0.y, a0.z, a0.w, a1.x, a1.y, a1.z, a1.w};
            float bv[4] = {b.x, b.y, b.z, b.w};
#pragma unroll
            for (int r = 0; r < 8; r++)
#pragma unroll
                for (int c2 = 0; c2 < 4; c2++)
                    acc[r][c2] = fmaf(av[r], bv[c2], acc[r][c2]);
        }
        if (!more) break;
        __syncthreads();
#pragma unroll
        for (int j = 0; j < 2; j++) {
            int c = tid + j * 128;
            int m = c >> 2, kb = (c & 3) * 4;
            As[kb + 0][m] = pa[j].x; As[kb + 1][m] = pa[j].y;
            As[kb + 2][m] = pa[j].z; As[kb + 3][m] = pa[j].w;
            *reinterpret_cast<float4*>(&Bs[c >> 4][(c & 15) * 4]) = pb[j];
        }
        __syncthreads();
    }
    float4 bv4 = ldf4(bias + col0 + tx * 4);
#pragma unroll
    for (int r = 0; r < 8; r++) {
        float4 v = make_float4(acc[r][0] + bv4.x, acc[r][1] + bv4.y,
                               acc[r][2] + bv4.z, acc[r][3] + bv4.w);
        *reinterpret_cast<float4*>(Z + (size_t)(row0 + ty * 8 + r) * 512 + col0 + tx * 4) = v;
    }
}

// argmax (first-occurrence) + logits emission (validated R4-R16).
__global__ void emit_kernel(const float* __restrict__ logits,
                            float* __restrict__ out, long long out_size)
{
    int row = blockIdx.x, tid = threadIdx.x;
    const float* lr = logits + (size_t)row * 512;
    float best = -3.402823466e38f; int bi = 0;
#pragma unroll
    for (int j = 0; j < 4; j++) {
        int vi = tid + j * 128; float v = lr[vi];
        if (v > best) { best = v; bi = vi; }
    }
    __shared__ float sv[128]; __shared__ int si[128];
    sv[tid] = best; si[tid] = bi;
    __syncthreads();
    for (int s = 64; s > 0; s >>= 1) {
        if (tid < s) {
            float v2 = sv[tid + s]; int i2 = si[tid + s];
            if (v2 > sv[tid] || (v2 == sv[tid] && i2 < si[tid])) { sv[tid] = v2; si[tid] = i2; }
        }
        __syncthreads();
    }
    int amax = si[0];
    if (out_size == BT_LL + BTV_LL) {
        if (tid == 0) out[row] = (float)amax;
        float* lo = out + BT_LL + (size_t)row * 512;
#pragma unroll
        for (int j = 0; j < 4; j++) lo[tid + j * 128] = lr[tid + j * 128];
    } else if (out_size == BTV_LL) {
        float* lo = out + (size_t)row * 512;
#pragma unroll
        for (int j = 0; j < 4; j++) lo[tid + j * 128] = lr[tid + j * 128];
    } else if (out_size == BT_LL) {
        if (tid == 0) reinterpret_cast<int*>(out)[row] = amax;
    } else {
        if (tid == 0 && (long long)row < out_size) out[row] = (float)amax;
#pragma unroll
        for (int j = 0; j < 4; j++) {
            long long o = BT_LL + (long long)row * 512 + tid + j * 128;
            if (o < out_size) out[o] = lr[tid + j * 128];
        }
    }
}

extern "C" void kernel_launch(void* const* d_in, const int* in_sizes, int n_in,
                              void* d_out, int out_size)
{
    Params p;
    const int* tokens = (const int*)d_in[0];
    const float* emb  = (const float*)d_in[1];
    for (int l = 0; l < 6; l++) {
        p.Wx[l] = (const float*)d_in[2 + l * 3];
        p.Wh[l] = (const float*)d_in[3 + l * 3];
        p.b[l]  = (const float*)d_in[4 + l * 3];
    }
    p.w_mean  = (const float*)d_in[20];
    p.b_mean  = (const float*)d_in[21];
    p.w_sigma = (const float*)d_in[22];
    p.b_sigma = (const float*)d_in[23];
    const float* dec_w = (const float*)d_in[24];
    const float* dec_b = (const float*)d_in[25];
    p.eps = (const float*)d_in[26];

    float *y, *lg;
    cudaGetSymbolAddress((void**)&y,  g_y);
    cudaGetSymbolAddress((void**)&lg, g_logits);

    prep_x<<<16384, 256>>>(tokens, emb);
    vae_persistent<<<NBLK, 256>>>(p);
    logits_gemm<<<dim3(8, 512), 128>>>(y, dec_w, dec_b, lg);
    emit_kernel<<<32768, 128>>>(lg, (float*)d_out, (long long)out_size);
}